// round 6
// baseline (speedup 1.0000x reference)
#include <cuda_runtime.h>
#include <cuda_fp16.h>
#include <cstdint>
#include <cstddef>

// ---------------------------------------------------------------------------
// out[32,28672] = (act[32,8192] @ weight[8192,28672] int8-valued) * scale[1,28672]
// Base-sm_103 ISA (tcgen05 unavailable, per R3 ptxas evidence).
// R5 evidence: rel_err 4.7e34 => harness widens f16->f32 (it has no f16 dtype).
// Runtime probes decide:  act/scale/out f32-widened vs native f16  (low-13-bit
// mantissa test, exact for widened f16), and weight int32-widened vs packed s8.
// Pipeline: 3-stage cp.async -> in-register s8->f16 dequant (PRMT + f16 bias)
// -> ldmatrix (.trans for B) -> mma.sync.m16n8k16.f32.f16.f16.f32.
// ---------------------------------------------------------------------------

#define MDIM 32
#define KDIM 8192
#define NDIM 28672

static constexpr int N_TILE  = 64;
static constexpr int K_CHUNK = 64;
static constexpr int CHUNKS  = KDIM / K_CHUNK;  // 128
static constexpr int STAGES  = 3;
static constexpr int THREADS = 128;
static constexpr int N_TILES = NDIM / N_TILE;   // 448

// Per-stage SMEM layout (bytes). f16 tiles padded to 144B/row: ldmatrix's
// 8-row phases then hit 8 distinct 16B bank groups (conflict-free).
static constexpr int RAW_OFF     = 0;       // raw weights: int32 64x256B (i8 path: 64x64B)
static constexpr int WF_OFF      = 16384;   // f16 weight tile: 64 rows * 144B
static constexpr int AF_OFF      = 25600;   // f16 act tile:    32 rows * 144B
static constexpr int STAGE_BYTES = 30208;
static constexpr int SMEM_TOTAL  = STAGE_BYTES * STAGES;  // 90624

// ---------------- device state / staging (no allocations allowed) ----------
__device__ int    g_w_is_i8;
__device__ int    g_act_is_f32;
__device__ __half g_act_f16[MDIM * KDIM];   // 512 KB
__device__ float  g_scale[NDIM];            // 112 KB

// ---------------- PTX helpers (base ISA only) -------------------------------
static __device__ __forceinline__ uint32_t smem_u32(const void* p) {
    uint32_t a;
    asm("{ .reg .u64 t; cvta.to.shared.u64 t, %1; cvt.u32.u64 %0, t; }" : "=r"(a) : "l"(p));
    return a;
}
static __device__ __forceinline__ void cp16(uint32_t dst, const void* src) {
    asm volatile("cp.async.cg.shared.global [%0], [%1], 16;" :: "r"(dst), "l"(src) : "memory");
}
static __device__ __forceinline__ void cp_commit() {
    asm volatile("cp.async.commit_group;" ::: "memory");
}
template <int N>
static __device__ __forceinline__ void cp_wait() {
    asm volatile("cp.async.wait_group %0;" :: "n"(N) : "memory");
}
static __device__ __forceinline__ void ldmatrix_x4(uint32_t* r, uint32_t addr) {
    asm volatile("ldmatrix.sync.aligned.m8n8.x4.shared.b16 {%0,%1,%2,%3}, [%4];"
                 : "=r"(r[0]), "=r"(r[1]), "=r"(r[2]), "=r"(r[3]) : "r"(addr));
}
static __device__ __forceinline__ void ldmatrix_x4_t(uint32_t* r, uint32_t addr) {
    asm volatile("ldmatrix.sync.aligned.m8n8.x4.trans.shared.b16 {%0,%1,%2,%3}, [%4];"
                 : "=r"(r[0]), "=r"(r[1]), "=r"(r[2]), "=r"(r[3]) : "r"(addr));
}
static __device__ __forceinline__ void mma16816(float* c, const uint32_t* a,
                                                uint32_t b0, uint32_t b1) {
    asm volatile(
        "mma.sync.aligned.m16n8k16.row.col.f32.f16.f16.f32 "
        "{%0,%1,%2,%3}, {%4,%5,%6,%7}, {%8,%9}, {%0,%1,%2,%3};"
        : "+f"(c[0]), "+f"(c[1]), "+f"(c[2]), "+f"(c[3])
        : "r"(a[0]), "r"(a[1]), "r"(a[2]), "r"(a[3]), "r"(b0), "r"(b1));
}
static __device__ __forceinline__ uint32_t prmt(uint32_t a, uint32_t b, uint32_t sel) {
    uint32_t d;
    asm("prmt.b32 %0, %1, %2, %3;" : "=r"(d) : "r"(a), "r"(b), "r"(sel));
    return d;
}
static __device__ __forceinline__ uint32_t subf16x2(uint32_t a, uint32_t b) {
    uint32_t d;
    asm("sub.rn.f16x2 %0, %1, %2;" : "=r"(d) : "r"(a), "r"(b));
    return d;
}
// 4 packed s8 -> 4 exact f16 (0x64XX = 1024+XX; minus 1152 => XX-128), store 8B.
static __device__ __forceinline__ void cvt_store(uint32_t dst, uint32_t p) {
    const uint32_t wx = p ^ 0x80808080u;              // s8 + 128 per byte
    uint32_t h01 = prmt(wx, 0x64646464u, 0x4140u);    // {b0,0x64, b1,0x64}
    uint32_t h23 = prmt(wx, 0x64646464u, 0x4342u);    // {b2,0x64, b3,0x64}
    h01 = subf16x2(h01, 0x64806480u);
    h23 = subf16x2(h23, 0x64806480u);
    asm volatile("st.shared.v2.b32 [%0], {%1, %2};" :: "r"(dst), "r"(h01), "r"(h23));
}

// ---------------- dtype probes -----------------------------------------------
__global__ void probe_kernel(const uint32_t* __restrict__ act_raw,
                             const int* __restrict__ w) {
    if (threadIdx.x == 0) {
        // f16->f32 widening is exact: low 13 mantissa bits of every word are 0.
        int nz = 0;
        for (int i = 0; i < 256; i++) nz += ((act_raw[i] & 0x1FFFu) != 0u);
        g_act_is_f32 = (nz < 8) ? 1 : 0;
        // int32-widened s8 stays in [-128,127]; packed-s8-as-int32 does not.
        int oor = 0;
        for (int i = 0; i < 256; i++) { const int v = w[i]; oor |= (v > 127) | (v < -128); }
        g_w_is_i8 = oor ? 1 : 0;
    }
}

// ---------------- act / scale staging ----------------------------------------
__global__ void __launch_bounds__(256) cvt_act_kernel(const void* __restrict__ act) {
    const int i = blockIdx.x * 256 + threadIdx.x;          // 65536 thr, 4 elems each
    if (g_act_is_f32) {
        const float4 v = ((const float4*)act)[i];
        __half2* d = (__half2*)(g_act_f16 + i * 4);
        d[0] = __floats2half2_rn(v.x, v.y);
        d[1] = __floats2half2_rn(v.z, v.w);
    } else {
        ((uint2*)g_act_f16)[i] = ((const uint2*)act)[i];
    }
}
__global__ void __launch_bounds__(256) cvt_scale_kernel(const void* __restrict__ scale) {
    const int i = blockIdx.x * 256 + threadIdx.x;          // 28672 threads
    if (i < NDIM)
        g_scale[i] = g_act_is_f32 ? ((const float*)scale)[i]
                                  : __half2float(((const __half*)scale)[i]);
}

// ---------------- stage fill (cp.async, one commit group) --------------------
static __device__ __forceinline__ void fill_stage(
    uint32_t sb, const char* wb, int n0, int kt, int s, int tid, int w_is_i8)
{
    const uint32_t rb = sb + s * STAGE_BYTES + RAW_OFF;
    if (w_is_i8) {
        // 64 k-rows x 64 bytes (packed s8)
#pragma unroll
        for (int i = 0; i < 2; i++) {
            const int idx = i * THREADS + tid;
            const int r = idx >> 2, c = idx & 3;
            cp16(rb + r * 64 + c * 16,
                 wb + (size_t)(kt * K_CHUNK + r) * NDIM + n0 + c * 16);
        }
    } else {
        // 64 k-rows x 256 bytes (int32-widened)
#pragma unroll
        for (int i = 0; i < 8; i++) {
            const int idx = i * THREADS + tid;
            const int r = idx >> 4, c = idx & 15;
            cp16(rb + r * 256 + c * 16,
                 wb + (((size_t)(kt * K_CHUNK + r) * NDIM + n0) << 2) + c * 16);
        }
    }
    const uint32_t ab = sb + s * STAGE_BYTES + AF_OFF;
    const char* actb = (const char*)g_act_f16;
#pragma unroll
    for (int i = 0; i < 2; i++) {
        const int idx = i * THREADS + tid;
        const int r = idx >> 3, c = idx & 7;
        cp16(ab + r * 144 + c * 16,
             actb + (size_t)r * (KDIM * 2) + kt * (K_CHUNK * 2) + c * 16);
    }
    cp_commit();
}

// ---------------- main GEMM --------------------------------------------------
__global__ void __launch_bounds__(THREADS, 2) gemm_kernel(
    const void* __restrict__ wgt, void* __restrict__ out)
{
    extern __shared__ char smem[];
    const uint32_t sb = smem_u32(smem);
    const int tid  = threadIdx.x;
    const int warp = tid >> 5;
    const int lane = tid & 31;
    const int n0   = blockIdx.x * N_TILE;
    const int w_is_i8   = g_w_is_i8;
    const int out_is_f32 = g_act_is_f32;

    const char* wb = (const char*)wgt;
    float c[2][2][4] = {};

#pragma unroll
    for (int p = 0; p < STAGES; p++)
        fill_stage(sb, wb, n0, p, p, tid, w_is_i8);

    const int l16 = lane & 15;
    const int lhi = (lane >> 4) * 16;

    for (int kt = 0; kt < CHUNKS; kt++) {
        const int s = kt % STAGES;

        const int rem = CHUNKS - 1 - kt;              // tail-safe wait ladder
        if (rem >= 2)      cp_wait<2>();
        else if (rem == 1) cp_wait<1>();
        else               cp_wait<0>();
        __syncthreads();

        // ---- convert raw weights -> f16 tile ----
        const uint32_t rb = sb + s * STAGE_BYTES + RAW_OFF;
        const uint32_t wf = sb + s * STAGE_BYTES + WF_OFF;
        if (w_is_i8) {
#pragma unroll
            for (int i = 0; i < 8; i++) {
                const int j = i * THREADS + tid;
                const int r = j >> 4, c4 = j & 15;
                uint32_t w;
                asm volatile("ld.shared.b32 %0, [%1];" : "=r"(w) : "r"(rb + r * 64 + c4 * 4));
                cvt_store(wf + r * 144 + c4 * 8, w);
            }
        } else {
#pragma unroll
            for (int i = 0; i < 8; i++) {
                const int j = i * THREADS + tid;
                const int r = j >> 4, c4 = j & 15;
                uint32_t vx, vy, vz, vw;
                asm volatile("ld.shared.v4.b32 {%0,%1,%2,%3}, [%4];"
                             : "=r"(vx), "=r"(vy), "=r"(vz), "=r"(vw)
                             : "r"(rb + r * 256 + c4 * 16));
                const uint32_t t = prmt(vx, vy, 0x4040u);   // low bytes of v0,v1
                const uint32_t u = prmt(vz, vw, 0x4040u);   // low bytes of v2,v3
                cvt_store(wf + r * 144 + c4 * 8, prmt(t, u, 0x5410u));
            }
        }
        __syncthreads();

        // ---- MMA: warp owns n cols [warp*16, warp*16+16) ----
        const uint32_t af = sb + s * STAGE_BYTES + AF_OFF;
#pragma unroll
        for (int ks = 0; ks < 4; ks++) {
            uint32_t b[4];
            ldmatrix_x4_t(b, wf + (uint32_t)(ks * 16 + l16) * 144 + warp * 32 + lhi);
#pragma unroll
            for (int mt = 0; mt < 2; mt++) {
                uint32_t a[4];
                ldmatrix_x4(a, af + (uint32_t)(mt * 16 + l16) * 144 + ks * 32 + lhi);
                mma16816(c[mt][0], a, b[0], b[1]);
                mma16816(c[mt][1], a, b[2], b[3]);
            }
        }
        __syncthreads();   // all warps done with stage s before refill

        if (kt + STAGES < CHUNKS)
            fill_stage(sb, wb, n0, kt + STAGES, s, tid, w_is_i8);
    }

    // ---- epilogue: scale, round through f16 (match reference), store ----
    const int nq    = (lane & 3) * 2;
    const int nbase = n0 + warp * 16;
    const float2 s0 = *(const float2*)&g_scale[nbase + nq];
    const float2 s1 = *(const float2*)&g_scale[nbase + 8 + nq];
#pragma unroll
    for (int mt = 0; mt < 2; mt++) {
        const int m0 = mt * 16 + (lane >> 2);
#pragma unroll
        for (int nt = 0; nt < 2; nt++) {
            const float2 sc = nt ? s1 : s0;
            const int n = nbase + nt * 8 + nq;
            const __half2 h0 = __floats2half2_rn(c[mt][nt][0] * sc.x, c[mt][nt][1] * sc.y);
            const __half2 h1 = __floats2half2_rn(c[mt][nt][2] * sc.x, c[mt][nt][3] * sc.y);
            if (out_is_f32) {
                float* o = (float*)out;
                *(float2*)(o + (size_t)m0 * NDIM + n)       = __half22float2(h0);
                *(float2*)(o + (size_t)(m0 + 8) * NDIM + n) = __half22float2(h1);
            } else {
                __half* o = (__half*)out;
                *(__half2*)(o + (size_t)m0 * NDIM + n)       = h0;
                *(__half2*)(o + (size_t)(m0 + 8) * NDIM + n) = h1;
            }
        }
    }
}

// ---------------- host side --------------------------------------------------
extern "C" void kernel_launch(void* const* d_in, const int* in_sizes, int n_in,
                              void* d_out, int out_size)
{
    const void* act   = d_in[0];
    const void* wgt   = d_in[1];
    const void* scale = d_in[2];

    probe_kernel<<<1, 32>>>((const uint32_t*)act, (const int*)wgt);
    cvt_act_kernel<<<(MDIM * KDIM / 4) / 256, 256>>>(act);
    cvt_scale_kernel<<<NDIM / 256, 256>>>(scale);

    cudaFuncSetAttribute(gemm_kernel, cudaFuncAttributeMaxDynamicSharedMemorySize, SMEM_TOTAL);
    gemm_kernel<<<N_TILES, THREADS, SMEM_TOTAL>>>(wgt, d_out);
}

// round 8
// speedup vs baseline: 1.0311x; 1.0311x over previous
#include <cuda_runtime.h>
#include <cuda_fp16.h>
#include <cstdint>
#include <cstddef>

// ---------------------------------------------------------------------------
// out[32,28672] = (act[32,8192] @ weight[8192,28672] int8-valued) * scale[1,28672]
// R6 evidence: weights are int32-widened (dur == 939MB/4.7TB/s), act/out f32.
// DRAM only 58.6% of spec at occ 11.4% => demand-starved. This round:
//   - no f16 weight SMEM tile: B fragments built in-register from raw int32
//     (PRMT low-byte merge + f16 magic bias, exact)
//   - 256 thr, N_TILE=128, K_CHUNK=32, 5-stage cp.async, 19.5KB/stage
//     => 2 CTAs/SM * 8 warps = 16 warps/SM, single wave (224 CTAs)
// ---------------------------------------------------------------------------

#define MDIM 32
#define KDIM 8192
#define NDIM 28672

static constexpr int N_TILE  = 128;
static constexpr int K_CHUNK = 32;
static constexpr int CHUNKS  = KDIM / K_CHUNK;  // 256
static constexpr int STAGES  = 5;
static constexpr int THREADS = 256;
static constexpr int N_TILES = NDIM / N_TILE;   // 224

// Per-stage SMEM (bytes).
// RAW int32 tile: 32 k-rows x 512B data, padded to 528B/row. 528/4=132 words;
//   fragment-gather banks = (132k + n) mod 32 = (4k + n) mod 32, k=2*tig even,
//   n=0..7 => all 32 banks distinct (conflict-free). 528 is 16B-multiple.
// RAW i8 fallback: 32 rows x 128B data, 144B pitch (within same buffer).
// ACT f16 tile: 32 m-rows x 64B data, 80B pitch (ldmatrix conflict-free:
//   20r mod 32 covers all bank groups).
static constexpr int RAW_OFF     = 0;
static constexpr int RAW_PITCH32 = 528;
static constexpr int RAW_PITCH8  = 144;
static constexpr int AF_OFF      = 32 * RAW_PITCH32;          // 16896
static constexpr int AF_PITCH    = 80;
static constexpr int STAGE_BYTES = AF_OFF + 32 * AF_PITCH;    // 19456
static constexpr int SMEM_TOTAL  = STAGE_BYTES * STAGES;      // 97280

// ---------------- device state / staging (no allocations allowed) ----------
__device__ int    g_w_is_i8;
__device__ int    g_act_is_f32;
__device__ __half g_act_f16[MDIM * KDIM];   // 512 KB
__device__ float  g_scale[NDIM];            // 112 KB

// ---------------- PTX helpers (base ISA only) -------------------------------
static __device__ __forceinline__ uint32_t smem_u32(const void* p) {
    uint32_t a;
    asm("{ .reg .u64 t; cvta.to.shared.u64 t, %1; cvt.u32.u64 %0, t; }" : "=r"(a) : "l"(p));
    return a;
}
static __device__ __forceinline__ void cp16(uint32_t dst, const void* src) {
    asm volatile("cp.async.cg.shared.global [%0], [%1], 16;" :: "r"(dst), "l"(src) : "memory");
}
static __device__ __forceinline__ void cp_commit() {
    asm volatile("cp.async.commit_group;" ::: "memory");
}
template <int N>
static __device__ __forceinline__ void cp_wait() {
    asm volatile("cp.async.wait_group %0;" :: "n"(N) : "memory");
}
static __device__ __forceinline__ void ldmatrix_x4(uint32_t* r, uint32_t addr) {
    asm volatile("ldmatrix.sync.aligned.m8n8.x4.shared.b16 {%0,%1,%2,%3}, [%4];"
                 : "=r"(r[0]), "=r"(r[1]), "=r"(r[2]), "=r"(r[3]) : "r"(addr));
}
static __device__ __forceinline__ void mma16816(float* c, const uint32_t* a,
                                                uint32_t b0, uint32_t b1) {
    asm volatile(
        "mma.sync.aligned.m16n8k16.row.col.f32.f16.f16.f32 "
        "{%0,%1,%2,%3}, {%4,%5,%6,%7}, {%8,%9}, {%0,%1,%2,%3};"
        : "+f"(c[0]), "+f"(c[1]), "+f"(c[2]), "+f"(c[3])
        : "r"(a[0]), "r"(a[1]), "r"(a[2]), "r"(a[3]), "r"(b0), "r"(b1));
}
static __device__ __forceinline__ uint32_t prmt(uint32_t a, uint32_t b, uint32_t sel) {
    uint32_t d;
    asm("prmt.b32 %0, %1, %2, %3;" : "=r"(d) : "r"(a), "r"(b), "r"(sel));
    return d;
}
static __device__ __forceinline__ uint32_t subf16x2(uint32_t a, uint32_t b) {
    uint32_t d;
    asm("sub.rn.f16x2 %0, %1, %2;" : "=r"(d) : "r"(a), "r"(b));
    return d;
}
static __device__ __forceinline__ uint32_t lds_b32(uint32_t addr) {
    uint32_t v;
    asm volatile("ld.shared.b32 %0, [%1];" : "=r"(v) : "r"(addr));
    return v;
}
static __device__ __forceinline__ uint32_t lds_u8(uint32_t addr) {
    uint32_t v;
    asm volatile("ld.shared.u8 %0, [%1];" : "=r"(v) : "r"(addr));
    return v;
}

// B fragment (packed f16x2 = {W[k][n], W[k+1][n]}) from raw int32 tile.
static __device__ __forceinline__ uint32_t bfrag_i32(uint32_t rb, int k, int n) {
    const uint32_t a0 = rb + (uint32_t)k * RAW_PITCH32 + (uint32_t)n * 4;
    const uint32_t v0 = lds_b32(a0);
    const uint32_t v1 = lds_b32(a0 + RAW_PITCH32);
    uint32_t m = prmt(v0, v1, 0x0040u);          // {v0.b0, v1.b0, -, -}
    m ^= 0x8080u;                                 // s8 + 128 per byte
    const uint32_t h = prmt(m, 0x64646464u, 0x4140u);  // {m.b0,0x64,m.b1,0x64}
    return subf16x2(h, 0x64806480u);              // 0x64XX - 1152 = XX-128 exact
}
// Same from packed-s8 tile (fallback).
static __device__ __forceinline__ uint32_t bfrag_i8(uint32_t rb, int k, int n) {
    const uint32_t a0 = rb + (uint32_t)k * RAW_PITCH8 + (uint32_t)n;
    const uint32_t v0 = lds_u8(a0) ^ 0x80u;
    const uint32_t v1 = lds_u8(a0 + RAW_PITCH8) ^ 0x80u;
    const uint32_t h  = 0x64006400u | v0 | (v1 << 16);
    return subf16x2(h, 0x64806480u);
}

// ---------------- dtype probes -----------------------------------------------
__global__ void probe_kernel(const uint32_t* __restrict__ act_raw,
                             const int* __restrict__ w) {
    if (threadIdx.x == 0) {
        int nz = 0;   // f16->f32 widening leaves low 13 mantissa bits zero
        for (int i = 0; i < 256; i++) nz += ((act_raw[i] & 0x1FFFu) != 0u);
        g_act_is_f32 = (nz < 8) ? 1 : 0;
        int oor = 0;  // int32-widened s8 stays in [-128,127]
        for (int i = 0; i < 256; i++) { const int v = w[i]; oor |= (v > 127) | (v < -128); }
        g_w_is_i8 = oor ? 1 : 0;
    }
}

// ---------------- act / scale staging ----------------------------------------
__global__ void __launch_bounds__(256) cvt_act_kernel(const void* __restrict__ act) {
    const int i = blockIdx.x * 256 + threadIdx.x;      // 65536 threads, 4 elems
    if (g_act_is_f32) {
        const float4 v = ((const float4*)act)[i];
        __half2* d = (__half2*)(g_act_f16 + i * 4);
        d[0] = __floats2half2_rn(v.x, v.y);
        d[1] = __floats2half2_rn(v.z, v.w);
    } else {
        ((uint2*)g_act_f16)[i] = ((const uint2*)act)[i];
    }
}
__global__ void __launch_bounds__(256) cvt_scale_kernel(const void* __restrict__ scale) {
    const int i = blockIdx.x * 256 + threadIdx.x;
    if (i < NDIM)
        g_scale[i] = g_act_is_f32 ? ((const float*)scale)[i]
                                  : __half2float(((const __half*)scale)[i]);
}

// ---------------- stage fill (one commit group) ------------------------------
template <int WI8>
static __device__ __forceinline__ void fill_stage(
    uint32_t sb, const char* wb, int n0, int kt, int s, int tid)
{
    const uint32_t rb = sb + s * STAGE_BYTES + RAW_OFF;
    if (WI8) {
        // 32 rows x 128B (packed s8)
        if (tid < 128) {
            const int r = tid >> 2, c = tid & 3;
            cp16(rb + r * RAW_PITCH8 + c * 16,
                 wb + (size_t)(kt * K_CHUNK + r) * NDIM + n0 + c * 16);
        }
    } else {
        // 32 rows x 512B (int32-widened)
#pragma unroll
        for (int i = 0; i < 4; i++) {
            const int idx = i * THREADS + tid;
            const int r = idx >> 5, c = idx & 31;
            cp16(rb + r * RAW_PITCH32 + c * 16,
                 wb + (((size_t)(kt * K_CHUNK + r) * NDIM + n0) << 2) + c * 16);
        }
    }
    const uint32_t ab = sb + s * STAGE_BYTES + AF_OFF;
    if (tid < 128) {
        const int r = tid >> 2, c = tid & 3;
        cp16(ab + r * AF_PITCH + c * 16,
             (const char*)g_act_f16 + (size_t)r * (KDIM * 2) + kt * (K_CHUNK * 2) + c * 16);
    }
    cp_commit();
}

// ---------------- mainloop body ----------------------------------------------
template <int WI8>
static __device__ __forceinline__ void run_mainloop(
    uint32_t sb, const char* wb, int n0, int tid, int warp, int lane,
    float c[2][2][4])
{
    const int l16 = lane & 15;
    const int lhi = (lane >> 4) * 16;
    const int gid = lane >> 2;     // n within n8 tile
    const int tig = lane & 3;      // k pair selector

#pragma unroll
    for (int p = 0; p < STAGES - 1; p++)
        fill_stage<WI8>(sb, wb, n0, p, p, tid);

    for (int kt = 0; kt < CHUNKS; kt++) {
        const int s = kt % STAGES;

        const int rem = CHUNKS - 1 - kt;          // tail-safe wait ladder
        if (rem >= 3)      cp_wait<3>();
        else if (rem == 2) cp_wait<2>();
        else if (rem == 1) cp_wait<1>();
        else               cp_wait<0>();
        __syncthreads();

        const uint32_t rb = sb + s * STAGE_BYTES + RAW_OFF;
        const uint32_t af = sb + s * STAGE_BYTES + AF_OFF;

#pragma unroll
        for (int ks = 0; ks < 2; ks++) {
            const int kb = ks * 16;
            uint32_t a0[4], a1[4];
            ldmatrix_x4(a0, af + (uint32_t)(l16) * AF_PITCH + ks * 32 + lhi);
            ldmatrix_x4(a1, af + (uint32_t)(16 + l16) * AF_PITCH + ks * 32 + lhi);
#pragma unroll
            for (int nt = 0; nt < 2; nt++) {
                const int n = warp * 16 + nt * 8 + gid;   // col within N_TILE
                uint32_t b0, b1;
                if (WI8) { b0 = bfrag_i8(rb, kb + tig * 2, n);
                           b1 = bfrag_i8(rb, kb + tig * 2 + 8, n); }
                else     { b0 = bfrag_i32(rb, kb + tig * 2, n);
                           b1 = bfrag_i32(rb, kb + tig * 2 + 8, n); }
                mma16816(c[0][nt], a0, b0, b1);
                mma16816(c[1][nt], a1, b0, b1);
            }
        }
        __syncthreads();   // all warps done with stage s before refill

        if (kt + STAGES - 1 < CHUNKS)
            fill_stage<WI8>(sb, wb, n0, kt + STAGES - 1, (kt + STAGES - 1) % STAGES, tid);
    }
}

// ---------------- main GEMM --------------------------------------------------
__global__ void __launch_bounds__(THREADS, 2) gemm_kernel(
    const void* __restrict__ wgt, void* __restrict__ out)
{
    extern __shared__ char smem[];
    const uint32_t sb = smem_u32(smem);
    const int tid  = threadIdx.x;
    const int warp = tid >> 5;
    const int lane = tid & 31;
    const int n0   = blockIdx.x * N_TILE;

    float c[2][2][4] = {};
    const char* wb = (const char*)wgt;

    if (g_w_is_i8) run_mainloop<1>(sb, wb, n0, tid, warp, lane, c);
    else           run_mainloop<0>(sb, wb, n0, tid, warp, lane, c);

    // ---- epilogue: scale, round through f16 (match reference), store ----
    const int out_is_f32 = g_act_is_f32;
    const int nq    = (lane & 3) * 2;
    const int nbase = n0 + warp * 16;
    const float2 s0 = *(const float2*)&g_scale[nbase + nq];
    const float2 s1 = *(const float2*)&g_scale[nbase + 8 + nq];
#pragma unroll
    for (int mt = 0; mt < 2; mt++) {
        const int m0 = mt * 16 + (lane >> 2);
#pragma unroll
        for (int nt = 0; nt < 2; nt++) {
            const float2 sc = nt ? s1 : s0;
            const int n = nbase + nt * 8 + nq;
            const __half2 h0 = __floats2half2_rn(c[mt][nt][0] * sc.x, c[mt][nt][1] * sc.y);
            const __half2 h1 = __floats2half2_rn(c[mt][nt][2] * sc.x, c[mt][nt][3] * sc.y);
            if (out_is_f32) {
                float* o = (float*)out;
                *(float2*)(o + (size_t)m0 * NDIM + n)       = __half22float2(h0);
                *(float2*)(o + (size_t)(m0 + 8) * NDIM + n) = __half22float2(h1);
            } else {
                __half* o = (__half*)out;
                *(__half2*)(o + (size_t)m0 * NDIM + n)       = h0;
                *(__half2*)(o + (size_t)(m0 + 8) * NDIM + n) = h1;
            }
        }
    }
}

// ---------------- host side --------------------------------------------------
extern "C" void kernel_launch(void* const* d_in, const int* in_sizes, int n_in,
                              void* d_out, int out_size)
{
    const void* act   = d_in[0];
    const void* wgt   = d_in[1];
    const void* scale = d_in[2];

    probe_kernel<<<1, 32>>>((const uint32_t*)act, (const int*)wgt);
    cvt_act_kernel<<<(MDIM * KDIM / 4) / 256, 256>>>(act);
    cvt_scale_kernel<<<(NDIM + 255) / 256, 256>>>(scale);

    cudaFuncSetAttribute(gemm_kernel, cudaFuncAttributeMaxDynamicSharedMemorySize, SMEM_TOTAL);
    gemm_kernel<<<N_TILES, THREADS, SMEM_TOTAL>>>(wgt, d_out);
}